// round 1
// baseline (speedup 1.0000x reference)
#include <cuda_runtime.h>

// out = joints @ R + t, R = RX(roll) @ RY(pitch) @ RZ(yaw)
// R rows (row i multiplies p[i], since result is p @ R):
//   r0 = [ cp*cy,            -cp*sy,            sp    ]
//   r1 = [ cr*sy + sr*sp*cy,  cr*cy - sr*sp*sy, -sr*cp]
//   r2 = [ sr*sy - cr*sp*cy,  sr*cy + cr*sp*sy,  cr*cp]

struct Rot {
    float r00, r01, r02;
    float r10, r11, r12;
    float r20, r21, r22;
    float tx, ty, tz;
};

__device__ __forceinline__ Rot make_rot(const float* __restrict__ ori,
                                        const float* __restrict__ trs) {
    float sr, cr, sp, cp, sy, cy;
    sincosf(ori[0], &sr, &cr);
    sincosf(ori[1], &sp, &cp);
    sincosf(ori[2], &sy, &cy);
    Rot R;
    R.r00 = cp * cy;                R.r01 = -cp * sy;               R.r02 = sp;
    R.r10 = cr * sy + sr * sp * cy; R.r11 = cr * cy - sr * sp * sy; R.r12 = -sr * cp;
    R.r20 = sr * sy - cr * sp * cy; R.r21 = sr * cy + cr * sp * sy; R.r22 = cr * cp;
    R.tx = trs[0]; R.ty = trs[1]; R.tz = trs[2];
    return R;
}

__device__ __forceinline__ void xform(const Rot& R, float x, float y, float z,
                                      float& ox, float& oy, float& oz) {
    ox = fmaf(x, R.r00, fmaf(y, R.r10, fmaf(z, R.r20, R.tx)));
    oy = fmaf(x, R.r01, fmaf(y, R.r11, fmaf(z, R.r21, R.ty)));
    oz = fmaf(x, R.r02, fmaf(y, R.r12, fmaf(z, R.r22, R.tz)));
}

// Each thread: 4 points = 12 floats = 3x float4 load + 3x float4 store.
__global__ void __launch_bounds__(256)
transform_vec4(const float4* __restrict__ in, float4* __restrict__ out,
               const float* __restrict__ ori, const float* __restrict__ trs,
               int nthreads) {
    int i = blockIdx.x * blockDim.x + threadIdx.x;
    if (i >= nthreads) return;

    // Front-batch the 3 global loads (MLP) before any trig dependency.
    long base = 3L * i;
    float4 a = in[base + 0];
    float4 b = in[base + 1];
    float4 c = in[base + 2];

    Rot R = make_rot(ori, trs);

    float4 oa, ob, oc;
    xform(R, a.x, a.y, a.z, oa.x, oa.y, oa.z);
    xform(R, a.w, b.x, b.y, oa.w, ob.x, ob.y);
    xform(R, b.z, b.w, c.x, ob.z, ob.w, oc.x);
    xform(R, c.y, c.z, c.w, oc.y, oc.z, oc.w);

    out[base + 0] = oa;
    out[base + 1] = ob;
    out[base + 2] = oc;
}

// Scalar tail: one thread per remaining point.
__global__ void transform_tail(const float* __restrict__ in, float* __restrict__ out,
                               const float* __restrict__ ori, const float* __restrict__ trs,
                               int start_pt, int n_pts) {
    int p = start_pt + blockIdx.x * blockDim.x + threadIdx.x;
    if (p >= n_pts) return;
    Rot R = make_rot(ori, trs);
    long o = 3L * p;
    float x = in[o], y = in[o + 1], z = in[o + 2];
    float ox, oy, oz;
    xform(R, x, y, z, ox, oy, oz);
    out[o] = ox; out[o + 1] = oy; out[o + 2] = oz;
}

extern "C" void kernel_launch(void* const* d_in, const int* in_sizes, int n_in,
                              void* d_out, int out_size) {
    const float* joints = (const float*)d_in[0];
    const float* ori    = (const float*)d_in[1];
    const float* trs    = (const float*)d_in[2];
    float* out = (float*)d_out;

    int n_floats = in_sizes[0];
    int n_points = n_floats / 3;
    int nthreads = n_points / 4;  // 4 points per thread

    if (nthreads > 0) {
        int blocks = (nthreads + 255) / 256;
        transform_vec4<<<blocks, 256>>>((const float4*)joints, (float4*)out,
                                        ori, trs, nthreads);
    }
    int done = nthreads * 4;
    int tail = n_points - done;
    if (tail > 0) {
        int blocks = (tail + 255) / 256;
        transform_tail<<<blocks, 256>>>(joints, out, ori, trs, done, n_points);
    }
}

// round 2
// speedup vs baseline: 1.0378x; 1.0378x over previous
#include <cuda_runtime.h>

// out = joints @ R + t, R = RX(roll) @ RY(pitch) @ RZ(yaw)
// R rows (row i multiplies p[i], since result is p @ R):
//   r0 = [ cp*cy,            -cp*sy,            sp    ]
//   r1 = [ cr*sy + sr*sp*cy,  cr*cy - sr*sp*sy, -sr*cp]
//   r2 = [ sr*sy - cr*sp*cy,  sr*cy + cr*sp*sy,  cr*cp]

struct Rot {
    float r00, r01, r02;
    float r10, r11, r12;
    float r20, r21, r22;
    float tx, ty, tz;
};

__device__ __forceinline__ Rot make_rot(const float* __restrict__ ori,
                                        const float* __restrict__ trs) {
    float sr, cr, sp, cp, sy, cy;
    sincosf(ori[0], &sr, &cr);
    sincosf(ori[1], &sp, &cp);
    sincosf(ori[2], &sy, &cy);
    Rot R;
    R.r00 = cp * cy;                R.r01 = -cp * sy;               R.r02 = sp;
    R.r10 = cr * sy + sr * sp * cy; R.r11 = cr * cy - sr * sp * sy; R.r12 = -sr * cp;
    R.r20 = sr * sy - cr * sp * cy; R.r21 = sr * cy + cr * sp * sy; R.r22 = cr * cp;
    R.tx = trs[0]; R.ty = trs[1]; R.tz = trs[2];
    return R;
}

__device__ __forceinline__ void xform(const Rot& R, float x, float y, float z,
                                      float& ox, float& oy, float& oz) {
    ox = fmaf(x, R.r00, fmaf(y, R.r10, fmaf(z, R.r20, R.tx)));
    oy = fmaf(x, R.r01, fmaf(y, R.r11, fmaf(z, R.r21, R.ty)));
    oz = fmaf(x, R.r02, fmaf(y, R.r12, fmaf(z, R.r22, R.tz)));
}

// Block = 256 threads, handles 768 contiguous float4s (= 1024 points).
// Global loads/stores fully coalesced; point regrouping happens in smem.
__global__ void __launch_bounds__(256)
transform_smem(const float4* __restrict__ in, float4* __restrict__ out,
               const float* __restrict__ ori, const float* __restrict__ trs) {
    __shared__ float4 s[768];
    const int t = threadIdx.x;
    const long base = (long)blockIdx.x * 768;

    // Coalesced loads: warp lanes hit consecutive float4s (4 lines / LDG).
    float4 l0 = in[base + t];
    float4 l1 = in[base + t + 256];
    float4 l2 = in[base + t + 512];

    // Trig overlaps the loads (MUFU, independent).
    Rot R = make_rot(ori, trs);

    s[t]       = l0;
    s[t + 256] = l1;
    s[t + 512] = l2;
    __syncthreads();

    // Private 3 float4s = 4 points. 48B stride -> conflict-free LDS.128.
    float4 a = s[3 * t + 0];
    float4 b = s[3 * t + 1];
    float4 c = s[3 * t + 2];

    float4 oa, ob, oc;
    xform(R, a.x, a.y, a.z, oa.x, oa.y, oa.z);
    xform(R, a.w, b.x, b.y, oa.w, ob.x, ob.y);
    xform(R, b.z, b.w, c.x, ob.z, ob.w, oc.x);
    xform(R, c.y, c.z, c.w, oc.y, oc.z, oc.w);

    s[3 * t + 0] = oa;
    s[3 * t + 1] = ob;
    s[3 * t + 2] = oc;
    __syncthreads();

    // Coalesced stores.
    out[base + t]       = s[t];
    out[base + t + 256] = s[t + 256];
    out[base + t + 512] = s[t + 512];
}

// Scalar tail: one thread per remaining point.
__global__ void transform_tail(const float* __restrict__ in, float* __restrict__ out,
                               const float* __restrict__ ori, const float* __restrict__ trs,
                               int start_pt, int n_pts) {
    int p = start_pt + blockIdx.x * blockDim.x + threadIdx.x;
    if (p >= n_pts) return;
    Rot R = make_rot(ori, trs);
    long o = 3L * p;
    float x = in[o], y = in[o + 1], z = in[o + 2];
    float ox, oy, oz;
    xform(R, x, y, z, ox, oy, oz);
    out[o] = ox; out[o + 1] = oy; out[o + 2] = oz;
}

extern "C" void kernel_launch(void* const* d_in, const int* in_sizes, int n_in,
                              void* d_out, int out_size) {
    const float* joints = (const float*)d_in[0];
    const float* ori    = (const float*)d_in[1];
    const float* trs    = (const float*)d_in[2];
    float* out = (float*)d_out;

    const int n_floats = in_sizes[0];
    const int n_points = n_floats / 3;

    // Each block consumes 3072 floats (1024 points) via the vectorized path.
    const int vec_blocks = n_floats / 3072;
    if (vec_blocks > 0) {
        transform_smem<<<vec_blocks, 256>>>((const float4*)joints, (float4*)out,
                                            ori, trs);
    }
    const int done = vec_blocks * 1024;
    const int tail = n_points - done;
    if (tail > 0) {
        int blocks = (tail + 255) / 256;
        transform_tail<<<blocks, 256>>>(joints, out, ori, trs, done, n_points);
    }
}